// round 4
// baseline (speedup 1.0000x reference)
#include <cuda_runtime.h>
#include <math.h>

#define B_ 2
#define T_ 2048
#define C_ 768
#define H_ 12
#define D_ 64
#define NLEFT 6
#define NK (C_ / 16)  // 48 BK-steps

// Scratch (module-scope device arrays; no runtime allocation).
__device__ float g_q[B_ * H_ * T_ * D_];
__device__ float g_k[B_ * H_ * T_ * D_];
__device__ float g_v[B_ * H_ * T_ * D_];
__device__ float g_ctx[B_ * T_ * C_];

// ---------------------------------------------------------------------------
// SGEMM core: 128x128 tile, BK=16, 256 threads, 8x8 micro-tile,
// 2-stage smem double buffering with ONE __syncthreads per BK step.
// Computes acc = A[row0:+128, :] @ W[col0:+128, :]^T  (K = C_ = 768)
// ---------------------------------------------------------------------------
#define GEMM_BODY(APTR, WPTR)                                                  \
  __shared__ float As[2][16][132];                                             \
  __shared__ float Bs[2][16][132];                                             \
  const int tid = threadIdx.x;                                                 \
  const int tx = tid & 15, ty = tid >> 4;                                      \
  const int row0 = blockIdx.y * 128;                                           \
  const int col0 = blockIdx.x * 128;                                           \
  const int lr = tid >> 1;          /* 0..127 */                               \
  const int lk8 = (tid & 1) * 8;    /* 0 or 8 */                               \
  float acc[8][8] = {};                                                        \
  const float* ap = (APTR) + (row0 + lr) * C_ + lk8;                           \
  const float* wp = (WPTR) + (col0 + lr) * C_ + lk8;                           \
  /* preload tile 0 */                                                         \
  {                                                                            \
    float4 a0 = *(const float4*)(ap);                                          \
    float4 a1 = *(const float4*)(ap + 4);                                      \
    float4 b0 = *(const float4*)(wp);                                          \
    float4 b1 = *(const float4*)(wp + 4);                                      \
    As[0][lk8 + 0][lr] = a0.x; As[0][lk8 + 1][lr] = a0.y;                      \
    As[0][lk8 + 2][lr] = a0.z; As[0][lk8 + 3][lr] = a0.w;                      \
    As[0][lk8 + 4][lr] = a1.x; As[0][lk8 + 5][lr] = a1.y;                      \
    As[0][lk8 + 6][lr] = a1.z; As[0][lk8 + 7][lr] = a1.w;                      \
    Bs[0][lk8 + 0][lr] = b0.x; Bs[0][lk8 + 1][lr] = b0.y;                      \
    Bs[0][lk8 + 2][lr] = b0.z; Bs[0][lk8 + 3][lr] = b0.w;                      \
    Bs[0][lk8 + 4][lr] = b1.x; Bs[0][lk8 + 5][lr] = b1.y;                      \
    Bs[0][lk8 + 6][lr] = b1.z; Bs[0][lk8 + 7][lr] = b1.w;                      \
  }                                                                            \
  __syncthreads();                                                             \
  for (int it = 0; it < NK; it++) {                                            \
    const int cur = it & 1, nxt = cur ^ 1;                                     \
    float4 a0, a1, b0, b1;                                                     \
    if (it + 1 < NK) {                                                         \
      const int k0 = (it + 1) * 16;                                            \
      a0 = *(const float4*)(ap + k0);                                          \
      a1 = *(const float4*)(ap + k0 + 4);                                      \
      b0 = *(const float4*)(wp + k0);                                          \
      b1 = *(const float4*)(wp + k0 + 4);                                      \
    }                                                                          \
    _Pragma("unroll")                                                          \
    for (int kk = 0; kk < 16; kk++) {                                          \
      float4 av0 = *(const float4*)&As[cur][kk][ty * 8];                       \
      float4 av1 = *(const float4*)&As[cur][kk][ty * 8 + 4];                   \
      float4 bv0 = *(const float4*)&Bs[cur][kk][tx * 8];                       \
      float4 bv1 = *(const float4*)&Bs[cur][kk][tx * 8 + 4];                   \
      float a[8] = {av0.x, av0.y, av0.z, av0.w, av1.x, av1.y, av1.z, av1.w};   \
      float b[8] = {bv0.x, bv0.y, bv0.z, bv0.w, bv1.x, bv1.y, bv1.z, bv1.w};   \
      _Pragma("unroll")                                                        \
      for (int i = 0; i < 8; i++)                                              \
        _Pragma("unroll")                                                      \
        for (int j = 0; j < 8; j++) acc[i][j] += a[i] * b[j];                  \
    }                                                                          \
    if (it + 1 < NK) {                                                         \
      As[nxt][lk8 + 0][lr] = a0.x; As[nxt][lk8 + 1][lr] = a0.y;                \
      As[nxt][lk8 + 2][lr] = a0.z; As[nxt][lk8 + 3][lr] = a0.w;                \
      As[nxt][lk8 + 4][lr] = a1.x; As[nxt][lk8 + 5][lr] = a1.y;                \
      As[nxt][lk8 + 6][lr] = a1.z; As[nxt][lk8 + 7][lr] = a1.w;                \
      Bs[nxt][lk8 + 0][lr] = b0.x; Bs[nxt][lk8 + 1][lr] = b0.y;                \
      Bs[nxt][lk8 + 2][lr] = b0.z; Bs[nxt][lk8 + 3][lr] = b0.w;                \
      Bs[nxt][lk8 + 4][lr] = b1.x; Bs[nxt][lk8 + 5][lr] = b1.y;                \
      Bs[nxt][lk8 + 6][lr] = b1.z; Bs[nxt][lk8 + 7][lr] = b1.w;                \
      __syncthreads();                                                         \
    }                                                                          \
  }

// GEMM 1: qkv[4096, 2304] = x @ Wqkv^T + b, scattered into g_q/g_k/g_v [B,H,T,D].
__global__ __launch_bounds__(256) void qkv_gemm_kernel(
    const float* __restrict__ x, const float* __restrict__ W,
    const float* __restrict__ bias) {
  GEMM_BODY(x, W)
  const int colbase = col0 + tx * 8;        // global col, 8-aligned
  const int three = colbase / C_;           // constant within the tile
  const int cm = colbase % C_;
  const int h = cm / D_;                    // constant per thread
  const int d0 = cm % D_;                   // 8-aligned, no boundary cross
  float* dst = (three == 0) ? g_q : ((three == 1) ? g_k : g_v);
  float bv[8];
#pragma unroll
  for (int j = 0; j < 8; j++) bv[j] = bias[colbase + j];
#pragma unroll
  for (int i = 0; i < 8; i++) {
    int n = row0 + ty * 8 + i;
    int bb = n >> 11;
    int t = n & (T_ - 1);
    float* p = &dst[(((bb * H_ + h) * T_) + t) * D_ + d0];
    float4 o0, o1;
    o0.x = acc[i][0] + bv[0]; o0.y = acc[i][1] + bv[1];
    o0.z = acc[i][2] + bv[2]; o0.w = acc[i][3] + bv[3];
    o1.x = acc[i][4] + bv[4]; o1.y = acc[i][5] + bv[5];
    o1.z = acc[i][6] + bv[6]; o1.w = acc[i][7] + bv[7];
    *(float4*)(p + 0) = o0;
    *(float4*)(p + 4) = o1;
  }
}

// GEMM 2: out[4096, 768] = g_ctx @ Wo^T + bias.
__global__ __launch_bounds__(256) void out_gemm_kernel(
    const float* __restrict__ W, const float* __restrict__ bias,
    float* __restrict__ out) {
  GEMM_BODY(g_ctx, W)
  const int colbase = col0 + tx * 8;
  float bv[8];
#pragma unroll
  for (int j = 0; j < 8; j++) bv[j] = bias[colbase + j];
#pragma unroll
  for (int i = 0; i < 8; i++) {
    int n = row0 + ty * 8 + i;
    float* p = &out[n * C_ + colbase];
    float4 o0, o1;
    o0.x = acc[i][0] + bv[0]; o0.y = acc[i][1] + bv[1];
    o0.z = acc[i][2] + bv[2]; o0.w = acc[i][3] + bv[3];
    o1.x = acc[i][4] + bv[4]; o1.y = acc[i][5] + bv[5];
    o1.z = acc[i][6] + bv[6]; o1.w = acc[i][7] + bv[7];
    *(float4*)(p + 0) = o0;
    *(float4*)(p + 4) = o1;
  }
}

// ---------------------------------------------------------------------------
// Flash attention (fp32): one CTA per (b, h, 64-row q tile), 128 threads,
// 8x4 micro-tile (ty: 8 x 8 q-rows, tx: 16 x 4 k-cols).
// Heads 0..5 causal (k <= q), heads 6..11 anti-causal (k >= q); only
// unmasked 64-key tiles are visited.
// Heavy-first scheduling: causal heads remap qb = 31 - bid.x so the
// highest-work CTAs of BOTH polarities launch at low bid.x, shrinking the
// final-wave straggler tail.
// ---------------------------------------------------------------------------
#define ATTN_SMEM_FLOATS (64 * 68 * 3 + 64 * 64)
#define ATTN_SMEM_BYTES (ATTN_SMEM_FLOATS * 4)

__device__ __forceinline__ float redmax16(float v) {
#pragma unroll
  for (int o = 8; o > 0; o >>= 1)
    v = fmaxf(v, __shfl_xor_sync(0xffffffffu, v, o));
  return v;
}
__device__ __forceinline__ float redsum16(float v) {
#pragma unroll
  for (int o = 8; o > 0; o >>= 1)
    v += __shfl_xor_sync(0xffffffffu, v, o);
  return v;
}

__global__ __launch_bounds__(128) void attn_kernel(const int* __restrict__ amask) {
  extern __shared__ float sm[];
  float* Qs = sm;                  // [d][q] stride 68
  float* Ks = sm + 64 * 68;        // [d][k] stride 68
  float* Ps = sm + 2 * 64 * 68;    // [q][k] stride 68
  float* Vs = sm + 3 * 64 * 68;    // [k][d] stride 64

  const int tid = threadIdx.x;
  const int tx = tid & 15, ty = tid >> 4;  // ty 0..7
  const int h = blockIdx.y;                // 0..11
  const int bb = blockIdx.z;               // 0..1
  const bool causal = (h < NLEFT);
  // Heavy-first: causal work = qb+1 tiles, anti-causal work = 32-qb tiles.
  const int qb = causal ? (31 - blockIdx.x) : blockIdx.x;

  const float* Qg = g_q + ((bb * H_ + h) * T_ + qb * 64) * D_;
  const float* Kg = g_k + ((bb * H_ + h) * T_) * D_;
  const float* Vg = g_v + ((bb * H_ + h) * T_) * D_;

  // Load Q tile transposed, pre-scaled by D^-0.5 = 1/8.
  {
    const int r = tid >> 1;             // 0..63
    const int dbase = (tid & 1) * 32;   // 0 or 32
#pragma unroll
    for (int u = 0; u < 8; u++) {
      float4 qv = *(const float4*)(Qg + r * D_ + dbase + u * 4);
      Qs[(dbase + u * 4 + 0) * 68 + r] = qv.x * 0.125f;
      Qs[(dbase + u * 4 + 1) * 68 + r] = qv.y * 0.125f;
      Qs[(dbase + u * 4 + 2) * 68 + r] = qv.z * 0.125f;
      Qs[(dbase + u * 4 + 3) * 68 + r] = qv.w * 0.125f;
    }
  }

  float m_i[8], l_i[8], acc[8][4];
#pragma unroll
  for (int i = 0; i < 8; i++) {
    m_i[i] = -3.0e38f;
    l_i[i] = 0.0f;
#pragma unroll
    for (int j = 0; j < 4; j++) acc[i][j] = 0.0f;
  }

  const int kb_begin = causal ? 0 : qb;
  const int kb_end = causal ? qb : 31;

  for (int kb = kb_begin; kb <= kb_end; kb++) {
    // Load K (transposed) + V tiles.
    {
      const int r = tid >> 1;
      const int dbase = (tid & 1) * 32;
#pragma unroll
      for (int u = 0; u < 8; u++) {
        float4 kv = *(const float4*)(Kg + (kb * 64 + r) * D_ + dbase + u * 4);
        Ks[(dbase + u * 4 + 0) * 68 + r] = kv.x;
        Ks[(dbase + u * 4 + 1) * 68 + r] = kv.y;
        Ks[(dbase + u * 4 + 2) * 68 + r] = kv.z;
        Ks[(dbase + u * 4 + 3) * 68 + r] = kv.w;
        float4 vv = *(const float4*)(Vg + (kb * 64 + r) * D_ + dbase + u * 4);
        *(float4*)&Vs[r * 64 + dbase + u * 4] = vv;
      }
    }
    __syncthreads();

    // S = (Q/8) @ K^T for this thread's 8x4.
    float s[8][4] = {};
#pragma unroll 8
    for (int d = 0; d < 64; d++) {
      float4 a0 = *(const float4*)&Qs[d * 68 + ty * 8];
      float4 a1 = *(const float4*)&Qs[d * 68 + ty * 8 + 4];
      float4 b4 = *(const float4*)&Ks[d * 68 + tx * 4];
      float a[8] = {a0.x, a0.y, a0.z, a0.w, a1.x, a1.y, a1.z, a1.w};
      float b[4] = {b4.x, b4.y, b4.z, b4.w};
#pragma unroll
      for (int i = 0; i < 8; i++)
#pragma unroll
        for (int j = 0; j < 4; j++) s[i][j] += a[i] * b[j];
    }

    // Masks: key padding + (anti)causal on the diagonal tile.
    const int kcol0 = kb * 64 + tx * 4;
    const int q0 = qb * 64 + ty * 8;
    float kpad[4];
#pragma unroll
    for (int j = 0; j < 4; j++)
      kpad[j] = (amask[bb * T_ + kcol0 + j] == 0) ? -3.0e38f : 0.0f;
#pragma unroll
    for (int i = 0; i < 8; i++)
#pragma unroll
      for (int j = 0; j < 4; j++) s[i][j] += kpad[j];
    if (kb == qb) {
#pragma unroll
      for (int i = 0; i < 8; i++)
#pragma unroll
        for (int j = 0; j < 4; j++) {
          int q = q0 + i, k = kcol0 + j;
          bool bad = causal ? (k > q) : (k < q);
          if (bad) s[i][j] = -3.0e38f;
        }
    }

    // Online softmax (row reductions over the 16 tx lanes).
#pragma unroll
    for (int i = 0; i < 8; i++) {
      float mt = fmaxf(fmaxf(s[i][0], s[i][1]), fmaxf(s[i][2], s[i][3]));
      mt = redmax16(mt);
      float mn = fmaxf(m_i[i], mt);
      float corr = __expf(m_i[i] - mn);
      m_i[i] = mn;
      float r = 0.0f;
#pragma unroll
      for (int j = 0; j < 4; j++) {
        float p = __expf(s[i][j] - mn);
        s[i][j] = p;
        r += p;
      }
      r = redsum16(r);
      l_i[i] = l_i[i] * corr + r;
#pragma unroll
      for (int j = 0; j < 4; j++) acc[i][j] *= corr;
    }

    // Write P to smem.
#pragma unroll
    for (int i = 0; i < 8; i++) {
      float4 p4 = make_float4(s[i][0], s[i][1], s[i][2], s[i][3]);
      *(float4*)&Ps[(ty * 8 + i) * 68 + tx * 4] = p4;
    }
    __syncthreads();

    // O += P @ V.
#pragma unroll 4
    for (int kk = 0; kk < 64; kk += 4) {
      float Pv[8][4];
#pragma unroll
      for (int i = 0; i < 8; i++)
        *(float4*)Pv[i] = *(const float4*)&Ps[(ty * 8 + i) * 68 + kk];
#pragma unroll
      for (int u = 0; u < 4; u++) {
        float4 v4 = *(const float4*)&Vs[(kk + u) * 64 + tx * 4];
        float v[4] = {v4.x, v4.y, v4.z, v4.w};
#pragma unroll
        for (int i = 0; i < 8; i++)
#pragma unroll
          for (int j = 0; j < 4; j++) acc[i][j] += Pv[i][u] * v[j];
      }
    }
    __syncthreads();
  }

  // Epilogue: normalize + write ctx[B, T, C].
  const int q0 = qb * 64 + ty * 8;
#pragma unroll
  for (int i = 0; i < 8; i++) {
    float inv = 1.0f / l_i[i];
    float4 o;
    o.x = acc[i][0] * inv;
    o.y = acc[i][1] * inv;
    o.z = acc[i][2] * inv;
    o.w = acc[i][3] * inv;
    *(float4*)&g_ctx[(bb * T_ + q0 + i) * C_ + h * D_ + tx * 4] = o;
  }
}

// ---------------------------------------------------------------------------
extern "C" void kernel_launch(void* const* d_in, const int* in_sizes, int n_in,
                              void* d_out, int out_size) {
  const float* x = (const float*)d_in[0];
  const int* amask = (const int*)d_in[1];
  const float* Wqkv_w = (const float*)d_in[2];
  const float* Wqkv_b = (const float*)d_in[3];
  const float* Wo_w = (const float*)d_in[4];
  const float* Wo_b = (const float*)d_in[5];
  float* out = (float*)d_out;

  cudaFuncSetAttribute(attn_kernel,
                       cudaFuncAttributeMaxDynamicSharedMemorySize,
                       ATTN_SMEM_BYTES);

  qkv_gemm_kernel<<<dim3(3 * C_ / 128, B_ * T_ / 128), 256>>>(x, Wqkv_w, Wqkv_b);
  attn_kernel<<<dim3(T_ / 64, H_, B_), 128, ATTN_SMEM_BYTES>>>(amask);
  out_gemm_kernel<<<dim3(C_ / 128, B_ * T_ / 128), 256>>>(Wo_w, Wo_b, out);
}

// round 15
// speedup vs baseline: 1.0964x; 1.0964x over previous
#include <cuda_runtime.h>
#include <math.h>

#define B_ 2
#define T_ 2048
#define C_ 768
#define H_ 12
#define D_ 64
#define NLEFT 6
#define NK (C_ / 16)  // 48 BK-steps
#define SP 132        // smem k-major stride; 132*4 % 16 == 0 (float4-aligned)

// Scratch (module-scope device arrays; no runtime allocation).
__device__ float g_q[B_ * H_ * T_ * D_];
__device__ float g_k[B_ * H_ * T_ * D_];
__device__ float g_v[B_ * H_ * T_ * D_];
__device__ float g_ctx[B_ * T_ * C_];

// ---------------------------------------------------------------------------
// SGEMM core: 128x128 tile, BK=16, 256 threads, 8x8 micro-tile,
// 2-stage smem double buffering, ONE __syncthreads per BK step.
// Loader mapping: lr = tid>>2 (8 rows/warp), kc = (tid&3)*4 — each warp's
// LDG.128 covers 8 rows x the full 64B k-slice => 8 cache lines (was 16).
// ---------------------------------------------------------------------------
#define GEMM_BODY(APTR, WPTR)                                                  \
  __shared__ float As[2][16][SP];                                              \
  __shared__ float Bs[2][16][SP];                                              \
  const int tid = threadIdx.x;                                                 \
  const int tx = tid & 15, ty = tid >> 4;                                      \
  const int row0 = blockIdx.y * 128;                                           \
  const int col0 = blockIdx.x * 128;                                           \
  const int lr = tid >> 2;          /* 0..63 */                                \
  const int kc = (tid & 3) * 4;     /* 0,4,8,12 */                             \
  float acc[8][8] = {};                                                        \
  const float* apA = (APTR) + (row0 + lr) * C_ + kc;                           \
  const float* apB = (APTR) + (row0 + lr + 64) * C_ + kc;                      \
  const float* wpA = (WPTR) + (col0 + lr) * C_ + kc;                           \
  const float* wpB = (WPTR) + (col0 + lr + 64) * C_ + kc;                      \
  /* preload tile 0 */                                                         \
  {                                                                            \
    float4 a0 = *(const float4*)(apA);                                         \
    float4 a1 = *(const float4*)(apB);                                         \
    float4 b0 = *(const float4*)(wpA);                                         \
    float4 b1 = *(const float4*)(wpB);                                         \
    As[0][kc + 0][lr] = a0.x; As[0][kc + 1][lr] = a0.y;                        \
    As[0][kc + 2][lr] = a0.z; As[0][kc + 3][lr] = a0.w;                        \
    As[0][kc + 0][lr + 64] = a1.x; As[0][kc + 1][lr + 64] = a1.y;              \
    As[0][kc + 2][lr + 64] = a1.z; As[0][kc + 3][lr + 64] = a1.w;              \
    Bs[0][kc + 0][lr] = b0.x; Bs[0][kc + 1][lr] = b0.y;                        \
    Bs[0][kc + 2][lr] = b0.z; Bs[0][kc + 3][lr] = b0.w;                        \
    Bs[0][kc + 0][lr + 64] = b1.x; Bs[0][kc + 1][lr + 64] = b1.y;              \
    Bs[0][kc + 2][lr + 64] = b1.z; Bs[0][kc + 3][lr + 64] = b1.w;              \
  }                                                                            \
  __syncthreads();                                                             \
  for (int it = 0; it < NK; it++) {                                            \
    const int cur = it & 1, nxt = cur ^ 1;                                     \
    float4 a0, a1, b0, b1;                                                     \
    if (it + 1 < NK) {                                                         \
      const int k0 = (it + 1) * 16;                                            \
      a0 = *(const float4*)(apA + k0);                                         \
      a1 = *(const float4*)(apB + k0);                                         \
      b0 = *(const float4*)(wpA + k0);                                         \
      b1 = *(const float4*)(wpB + k0);                                         \
    }                                                                          \
    _Pragma("unroll")                                                          \
    for (int kk = 0; kk < 16; kk++) {                                          \
      float4 av0 = *(const float4*)&As[cur][kk][ty * 8];                       \
      float4 av1 = *(const float4*)&As[cur][kk][ty * 8 + 4];                   \
      float4 bv0 = *(const float4*)&Bs[cur][kk][tx * 8];                       \
      float4 bv1 = *(const float4*)&Bs[cur][kk][tx * 8 + 4];                   \
      float a[8] = {av0.x, av0.y, av0.z, av0.w, av1.x, av1.y, av1.z, av1.w};   \
      float b[8] = {bv0.x, bv0.y, bv0.z, bv0.w, bv1.x, bv1.y, bv1.z, bv1.w};   \
      _Pragma("unroll")                                                        \
      for (int i = 0; i < 8; i++)                                              \
        _Pragma("unroll")                                                      \
        for (int j = 0; j < 8; j++) acc[i][j] += a[i] * b[j];                  \
    }                                                                          \
    if (it + 1 < NK) {                                                         \
      As[nxt][kc + 0][lr] = a0.x; As[nxt][kc + 1][lr] = a0.y;                  \
      As[nxt][kc + 2][lr] = a0.z; As[nxt][kc + 3][lr] = a0.w;                  \
      As[nxt][kc + 0][lr + 64] = a1.x; As[nxt][kc + 1][lr + 64] = a1.y;        \
      As[nxt][kc + 2][lr + 64] = a1.z; As[nxt][kc + 3][lr + 64] = a1.w;        \
      Bs[nxt][kc + 0][lr] = b0.x; Bs[nxt][kc + 1][lr] = b0.y;                  \
      Bs[nxt][kc + 2][lr] = b0.z; Bs[nxt][kc + 3][lr] = b0.w;                  \
      Bs[nxt][kc + 0][lr + 64] = b1.x; Bs[nxt][kc + 1][lr + 64] = b1.y;        \
      Bs[nxt][kc + 2][lr + 64] = b1.z; Bs[nxt][kc + 3][lr + 64] = b1.w;        \
      __syncthreads();                                                         \
    }                                                                          \
  }

// GEMM 1: qkv[4096, 2304] = x @ Wqkv^T + b, scattered into g_q/g_k/g_v [B,H,T,D].
__global__ __launch_bounds__(256) void qkv_gemm_kernel(
    const float* __restrict__ x, const float* __restrict__ W,
    const float* __restrict__ bias) {
  GEMM_BODY(x, W)
  const int colbase = col0 + tx * 8;        // global col, 8-aligned
  const int three = colbase / C_;
  const int cm = colbase % C_;
  const int h = cm / D_;
  const int d0 = cm % D_;                   // 8-aligned, no boundary cross
  float* dst = (three == 0) ? g_q : ((three == 1) ? g_k : g_v);
  float bv[8];
#pragma unroll
  for (int j = 0; j < 8; j++) bv[j] = bias[colbase + j];
#pragma unroll
  for (int i = 0; i < 8; i++) {
    int n = row0 + ty * 8 + i;
    int bb = n >> 11;
    int t = n & (T_ - 1);
    float* p = &dst[(((bb * H_ + h) * T_) + t) * D_ + d0];
    float4 o0, o1;
    o0.x = acc[i][0] + bv[0]; o0.y = acc[i][1] + bv[1];
    o0.z = acc[i][2] + bv[2]; o0.w = acc[i][3] + bv[3];
    o1.x = acc[i][4] + bv[4]; o1.y = acc[i][5] + bv[5];
    o1.z = acc[i][6] + bv[6]; o1.w = acc[i][7] + bv[7];
    *(float4*)(p + 0) = o0;
    *(float4*)(p + 4) = o1;
  }
}

// GEMM 2: out[4096, 768] = g_ctx @ Wo^T + bias.
__global__ __launch_bounds__(256) void out_gemm_kernel(
    const float* __restrict__ W, const float* __restrict__ bias,
    float* __restrict__ out) {
  GEMM_BODY(g_ctx, W)
  const int colbase = col0 + tx * 8;
  float bv[8];
#pragma unroll
  for (int j = 0; j < 8; j++) bv[j] = bias[colbase + j];
#pragma unroll
  for (int i = 0; i < 8; i++) {
    int n = row0 + ty * 8 + i;
    float* p = &out[n * C_ + colbase];
    float4 o0, o1;
    o0.x = acc[i][0] + bv[0]; o0.y = acc[i][1] + bv[1];
    o0.z = acc[i][2] + bv[2]; o0.w = acc[i][3] + bv[3];
    o1.x = acc[i][4] + bv[4]; o1.y = acc[i][5] + bv[5];
    o1.z = acc[i][6] + bv[6]; o1.w = acc[i][7] + bv[7];
    *(float4*)(p + 0) = o0;
    *(float4*)(p + 4) = o1;
  }
}

// ---------------------------------------------------------------------------
// Flash attention (fp32): one CTA per (b, h, 128-row q tile), 256 threads,
// 8x4 micro-tile (ty: 16 x 8 q-rows = 128, tx: 16 x 4 k-cols = 64).
// K/V tiles amortized over 2x the q-rows vs the 64-row version.
// Heads 0..5 causal (k <= q), heads 6..11 anti-causal (k >= q); only
// unmasked 64-key tiles visited. Heavy-first CTA order.
// Smem: Qs^T[64][132], Ks^T[64][68], Ps[128][68], Vs[64][64] = 100 KB.
// ---------------------------------------------------------------------------
#define ATTN_SMEM_FLOATS (64 * 132 + 64 * 68 + 128 * 68 + 64 * 64)
#define ATTN_SMEM_BYTES (ATTN_SMEM_FLOATS * 4)

__device__ __forceinline__ float redmax16(float v) {
#pragma unroll
  for (int o = 8; o > 0; o >>= 1)
    v = fmaxf(v, __shfl_xor_sync(0xffffffffu, v, o));
  return v;
}
__device__ __forceinline__ float redsum16(float v) {
#pragma unroll
  for (int o = 8; o > 0; o >>= 1)
    v += __shfl_xor_sync(0xffffffffu, v, o);
  return v;
}

__global__ __launch_bounds__(256, 2) void attn_kernel(const int* __restrict__ amask) {
  extern __shared__ float sm[];
  float* Qs = sm;                        // [d][q] stride 132
  float* Ks = sm + 64 * 132;             // [d][k] stride 68
  float* Ps = sm + 64 * 132 + 64 * 68;   // [q][k] stride 68
  float* Vs = Ps + 128 * 68;             // [k][d] stride 64

  const int tid = threadIdx.x;
  const int tx = tid & 15, ty = tid >> 4;  // ty 0..15
  const int h = blockIdx.y;                // 0..11
  const int bb = blockIdx.z;               // 0..1
  const bool causal = (h < NLEFT);
  // Heavy-first: causal work = 2qb+2 tiles, anti = 32-2qb tiles.
  const int qb = causal ? (15 - blockIdx.x) : blockIdx.x;  // 0..15

  const float* Qg = g_q + ((bb * H_ + h) * T_ + qb * 128) * D_;
  const float* Kg = g_k + ((bb * H_ + h) * T_) * D_;
  const float* Vg = g_v + ((bb * H_ + h) * T_) * D_;

  // Load Q tile (128x64) transposed, pre-scaled by D^-0.5 = 1/8.
  {
    const int r = tid >> 1;             // 0..127
    const int dbase = (tid & 1) * 32;   // 0 or 32
#pragma unroll
    for (int u = 0; u < 8; u++) {
      float4 qv = *(const float4*)(Qg + r * D_ + dbase + u * 4);
      Qs[(dbase + u * 4 + 0) * 132 + r] = qv.x * 0.125f;
      Qs[(dbase + u * 4 + 1) * 132 + r] = qv.y * 0.125f;
      Qs[(dbase + u * 4 + 2) * 132 + r] = qv.z * 0.125f;
      Qs[(dbase + u * 4 + 3) * 132 + r] = qv.w * 0.125f;
    }
  }

  float m_i[8], l_i[8], acc[8][4];
#pragma unroll
  for (int i = 0; i < 8; i++) {
    m_i[i] = -3.0e38f;
    l_i[i] = 0.0f;
#pragma unroll
    for (int j = 0; j < 4; j++) acc[i][j] = 0.0f;
  }

  const int kb_begin = causal ? 0 : (2 * qb);
  const int kb_end = causal ? (2 * qb + 1) : 31;
  const int diag_lo = 2 * qb;  // tiles overlapping the diagonal: diag_lo, diag_lo+1

  for (int kb = kb_begin; kb <= kb_end; kb++) {
    // Load K (64x64, transposed) + V (64x64) tiles with 256 threads.
    {
      const int r = tid >> 2;             // 0..63
      const int dbase = (tid & 3) * 16;   // 0,16,32,48
#pragma unroll
      for (int u = 0; u < 4; u++) {
        float4 kv = *(const float4*)(Kg + (kb * 64 + r) * D_ + dbase + u * 4);
        Ks[(dbase + u * 4 + 0) * 68 + r] = kv.x;
        Ks[(dbase + u * 4 + 1) * 68 + r] = kv.y;
        Ks[(dbase + u * 4 + 2) * 68 + r] = kv.z;
        Ks[(dbase + u * 4 + 3) * 68 + r] = kv.w;
        float4 vv = *(const float4*)(Vg + (kb * 64 + r) * D_ + dbase + u * 4);
        *(float4*)&Vs[r * 64 + dbase + u * 4] = vv;
      }
    }
    __syncthreads();

    // S = (Q/8) @ K^T for this thread's 8x4.
    float s[8][4] = {};
#pragma unroll 8
    for (int d = 0; d < 64; d++) {
      float4 a0 = *(const float4*)&Qs[d * 132 + ty * 8];
      float4 a1 = *(const float4*)&Qs[d * 132 + ty * 8 + 4];
      float4 b4 = *(const float4*)&Ks[d * 68 + tx * 4];
      float a[8] = {a0.x, a0.y, a0.z, a0.w, a1.x, a1.y, a1.z, a1.w};
      float b[4] = {b4.x, b4.y, b4.z, b4.w};
#pragma unroll
      for (int i = 0; i < 8; i++)
#pragma unroll
        for (int j = 0; j < 4; j++) s[i][j] += a[i] * b[j];
    }

    // Masks: key padding + (anti)causal on diagonal-overlapping tiles.
    const int kcol0 = kb * 64 + tx * 4;
    const int q0 = qb * 128 + ty * 8;
    float kpad[4];
#pragma unroll
    for (int j = 0; j < 4; j++)
      kpad[j] = (amask[bb * T_ + kcol0 + j] == 0) ? -3.0e38f : 0.0f;
#pragma unroll
    for (int i = 0; i < 8; i++)
#pragma unroll
      for (int j = 0; j < 4; j++) s[i][j] += kpad[j];
    if (kb == diag_lo || kb == diag_lo + 1) {
#pragma unroll
      for (int i = 0; i < 8; i++)
#pragma unroll
        for (int j = 0; j < 4; j++) {
          int q = q0 + i, k = kcol0 + j;
          bool bad = causal ? (k > q) : (k < q);
          if (bad) s[i][j] = -3.0e38f;
        }
    }

    // Online softmax (row reductions over the 16 tx lanes).
#pragma unroll
    for (int i = 0; i < 8; i++) {
      float mt = fmaxf(fmaxf(s[i][0], s[i][1]), fmaxf(s[i][2], s[i][3]));
      mt = redmax16(mt);
      float mn = fmaxf(m_i[i], mt);
      float corr = __expf(m_i[i] - mn);
      m_i[i] = mn;
      float r = 0.0f;
#pragma unroll
      for (int j = 0; j < 4; j++) {
        float p = __expf(s[i][j] - mn);
        s[i][j] = p;
        r += p;
      }
      r = redsum16(r);
      l_i[i] = l_i[i] * corr + r;
#pragma unroll
      for (int j = 0; j < 4; j++) acc[i][j] *= corr;
    }

    // Write P to smem.
#pragma unroll
    for (int i = 0; i < 8; i++) {
      float4 p4 = make_float4(s[i][0], s[i][1], s[i][2], s[i][3]);
      *(float4*)&Ps[(ty * 8 + i) * 68 + tx * 4] = p4;
    }
    __syncthreads();

    // O += P @ V.
#pragma unroll 4
    for (int kk = 0; kk < 64; kk += 4) {
      float Pv[8][4];
#pragma unroll
      for (int i = 0; i < 8; i++)
        *(float4*)Pv[i] = *(const float4*)&Ps[(ty * 8 + i) * 68 + kk];
#pragma unroll
      for (int u = 0; u < 4; u++) {
        float4 v4 = *(const float4*)&Vs[(kk + u) * 64 + tx * 4];
        float v[4] = {v4.x, v4.y, v4.z, v4.w};
#pragma unroll
        for (int i = 0; i < 8; i++)
#pragma unroll
          for (int j = 0; j < 4; j++) acc[i][j] += Pv[i][u] * v[j];
      }
    }
    __syncthreads();
  }

  // Epilogue: normalize + write ctx[B, T, C].
  const int q0 = qb * 128 + ty * 8;
#pragma unroll
  for (int i = 0; i < 8; i++) {
    float inv = 1.0f / l_i[i];
    float4 o;
    o.x = acc[i][0] * inv;
    o.y = acc[i][1] * inv;
    o.z = acc[i][2] * inv;
    o.w = acc[i][3] * inv;
    *(float4*)&g_ctx[(bb * T_ + q0 + i) * C_ + h * D_ + tx * 4] = o;
  }
}

// ---------------------------------------------------------------------------
extern "C" void kernel_launch(void* const* d_in, const int* in_sizes, int n_in,
                              void* d_out, int out_size) {
  const float* x = (const float*)d_in[0];
  const int* amask = (const int*)d_in[1];
  const float* Wqkv_w = (const float*)d_in[2];
  const float* Wqkv_b = (const float*)d_in[3];
  const float* Wo_w = (const float*)d_in[4];
  const float* Wo_b = (const float*)d_in[5];
  float* out = (float*)d_out;

  cudaFuncSetAttribute(attn_kernel,
                       cudaFuncAttributeMaxDynamicSharedMemorySize,
                       ATTN_SMEM_BYTES);

  qkv_gemm_kernel<<<dim3(3 * C_ / 128, B_ * T_ / 128), 256>>>(x, Wqkv_w, Wqkv_b);
  attn_kernel<<<dim3(T_ / 128, H_, B_), 256, ATTN_SMEM_BYTES>>>(amask);
  out_gemm_kernel<<<dim3(C_ / 128, B_ * T_ / 128), 256>>>(Wo_w, Wo_b, out);
}